// round 1
// baseline (speedup 1.0000x reference)
#include <cuda_runtime.h>

// Precomputed sorted codebook + midpoints (recomputed every launch; deterministic).
__device__ float g_sorted[128];
__device__ float g_mid[127];

// ---------------------------------------------------------------------------
// Prep: sort the 128-entry codebook by rank (O(128^2), one block, trivial cost)
// and build the 127 decision midpoints.
// ---------------------------------------------------------------------------
__global__ void vq_prep(const float* __restrict__ w) {
    __shared__ float sw[128];
    __shared__ float ss[128];
    int i = threadIdx.x;
    sw[i] = w[i];
    __syncthreads();
    float v = sw[i];
    int rank = 0;
#pragma unroll
    for (int k = 0; k < 128; ++k) {
        float u = sw[k];
        rank += ((u < v) || (u == v && k < i)) ? 1 : 0;
    }
    ss[rank] = v;          // ranks are unique (ties broken by index)
    __syncthreads();
    g_sorted[i] = ss[i];
    if (i < 127) g_mid[i] = 0.5f * (ss[i] + ss[i + 1]);
}

// ---------------------------------------------------------------------------
// Main kernel: per element, branchless lower_bound over 127 midpoints.
// Top 3 tree levels live in registers; levels 4-7 + final gather read from
// 32x-replicated shared tables laid out [j][lane] so bank == lane always
// (strictly conflict-free for arbitrary per-lane indices).
// ---------------------------------------------------------------------------
#define VQ_BLOCK 1024

__global__ __launch_bounds__(VQ_BLOCK, 2)
void vq_kernel(const float4* __restrict__ x4, float4* __restrict__ o4, int n4,
               const float* __restrict__ xt, float* __restrict__ ot, int n_tail) {
    __shared__ float smid[127][32];
    __shared__ float scode[128][32];

    const int tid = threadIdx.x;

    // Fill replicated tables (coalesced, conflict-free: consecutive words).
    for (int i = tid; i < 127 * 32; i += VQ_BLOCK)
        smid[i >> 5][i & 31] = g_mid[i >> 5];
    for (int i = tid; i < 128 * 32; i += VQ_BLOCK)
        scode[i >> 5][i & 31] = g_sorted[i >> 5];
    __syncthreads();

    const int lane = tid & 31;

    // Register-resident top 3 levels of the midpoint tree.
    const float m63  = smid[63][lane];
    const float m31  = smid[31][lane];
    const float m95  = smid[95][lane];
    const float m15  = smid[15][lane];
    const float m47  = smid[47][lane];
    const float m79  = smid[79][lane];
    const float m111 = smid[111][lane];

    const int idx = blockIdx.x * VQ_BLOCK + tid;
    if (idx < n4) {
        float4 v = x4[idx];
        float xs[4] = {v.x, v.y, v.z, v.w};
        float rr[4];
#pragma unroll
        for (int e = 0; e < 4; ++e) {
            const float xv = xs[e];
            // steps 1-3 in registers
            const bool p1 = (m63 < xv);
            int base = p1 ? 64 : 0;
            const float t2 = p1 ? m95 : m31;
            const bool p2 = (t2 < xv);
            base += p2 ? 32 : 0;
            const float t3 = p1 ? (p2 ? m111 : m79) : (p2 ? m47 : m15);
            base += (t3 < xv) ? 16 : 0;
            // steps 4-7 in conflict-free replicated smem
#pragma unroll
            for (int half = 8; half >= 1; half >>= 1) {
                const float m = smid[base + half - 1][lane];
                base += (m < xv) ? half : 0;
            }
            rr[e] = scode[base][lane];  // conflict-free gather
        }
        float4 ov;
        ov.x = rr[0]; ov.y = rr[1]; ov.z = rr[2]; ov.w = rr[3];
        o4[idx] = ov;
    }

    // Tail (n % 4 elements), handled by one thread; negligible.
    if (blockIdx.x == 0 && tid == 0 && n_tail > 0) {
        for (int t = 0; t < n_tail; ++t) {
            const float xv = xt[t];
            int base = 0;
#pragma unroll
            for (int half = 64; half >= 1; half >>= 1) {
                const float m = smid[base + half - 1][0];
                base += (m < xv) ? half : 0;
            }
            ot[t] = scode[base][0];
        }
    }
}

extern "C" void kernel_launch(void* const* d_in, const int* in_sizes, int n_in,
                              void* d_out, int out_size) {
    const float* x = (const float*)d_in[0];   // [16,1,512,512] fp32
    const float* w = (const float*)d_in[1];   // [128,1] fp32
    float* out = (float*)d_out;

    const int n = out_size;          // == in_sizes[0]
    const int n4 = n >> 2;
    const int n_tail = n & 3;

    vq_prep<<<1, 128>>>(w);

    const int grid = (n4 + VQ_BLOCK - 1) / VQ_BLOCK;
    vq_kernel<<<grid, VQ_BLOCK>>>((const float4*)x, (float4*)out, n4,
                                  x + (size_t)n4 * 4, out + (size_t)n4 * 4, n_tail);
}